// round 16
// baseline (speedup 1.0000x reference)
#include <cuda_runtime.h>
#include <cuda_fp16.h>

#define B_ 4
#define N_ 4096
#define D_ 256

// Device-global scratch (allocation-free rule)
static __device__ __half  g_vhi[B_ * N_ * D_];      // [b][n][d] fp16 hi
static __device__ __half  g_vlo[B_ * N_ * D_];      // fp16 lo residual
static __device__ __half  g_pthi[B_ * D_ * N_];     // [b][e][m]  P transposed, fp16
static __device__ __half  g_E[(size_t)B_ * N_ * N_];// [b][n][m]  edges, fp16 (134MB)

// ---------------- PTX helpers ----------------
__device__ __forceinline__ unsigned smem_u32(const void* p) {
    unsigned a;
    asm("{ .reg .u64 t; cvta.to.shared.u64 t, %1; cvt.u32.u64 %0, t; }" : "=r"(a) : "l"(p));
    return a;
}
__device__ __forceinline__ void cpa16(unsigned dst, const void* src) {
    asm volatile("cp.async.cg.shared.global [%0], [%1], 16;" :: "r"(dst), "l"(src) : "memory");
}
#define CP_COMMIT() asm volatile("cp.async.commit_group;" ::: "memory")
#define CP_WAIT0()  asm volatile("cp.async.wait_group 0;" ::: "memory")

__device__ __forceinline__ void ldm4(unsigned* r, unsigned addr) {
    asm volatile("ldmatrix.sync.aligned.m8n8.x4.shared.b16 {%0,%1,%2,%3}, [%4];"
                 : "=r"(r[0]), "=r"(r[1]), "=r"(r[2]), "=r"(r[3]) : "r"(addr));
}
__device__ __forceinline__ void mmah(float* d, const unsigned* a, unsigned b0, unsigned b1) {
    asm volatile(
        "mma.sync.aligned.m16n8k16.row.col.f32.f16.f16.f32 "
        "{%0,%1,%2,%3}, {%4,%5,%6,%7}, {%8,%9}, {%0,%1,%2,%3};"
        : "+f"(d[0]), "+f"(d[1]), "+f"(d[2]), "+f"(d[3])
        : "r"(a[0]), "r"(a[1]), "r"(a[2]), "r"(a[3]), "r"(b0), "r"(b1));
}
__device__ __forceinline__ void sts32(unsigned addr, unsigned v) {
    asm volatile("st.shared.u32 [%0], %1;" :: "r"(addr), "r"(v) : "memory");
}
__device__ __forceinline__ unsigned lds32(unsigned addr) {
    unsigned v;
    asm volatile("ld.shared.u32 %0, [%1];" : "=r"(v) : "r"(addr));
    return v;
}
__device__ __forceinline__ unsigned pack_h2(float x, float y) {
    __half2 h; h.x = __float2half_rn(x); h.y = __float2half_rn(y);
    return *(unsigned*)&h;
}
__device__ __forceinline__ float softsign(float s) {
    return __fdividef(s, 1.f + fabsf(s));
}

// ---------------- prologue ----------------
__device__ __forceinline__ unsigned long long ffma2(unsigned long long a,
                                                    unsigned long long b,
                                                    unsigned long long c) {
    unsigned long long d;
    asm("fma.rn.f32x2 %0, %1, %2, %3;" : "=l"(d) : "l"(a), "l"(b), "l"(c));
    return d;
}
__device__ __forceinline__ unsigned long long dup2(float x) {
    unsigned long long d;
    asm("mov.b64 %0, {%1, %1};" : "=l"(d) : "f"(x));
    return d;
}
union V4 { float4 f; unsigned long long u[2]; };

// proj + transpose + fp16 convert fused: writes g_pthi[b][e][m] directly
__global__ __launch_bounds__(256, 2)
void proj_kernel(const float* __restrict__ val, const float* __restrict__ Wv) {
    __shared__ float As[64 * 36];
    __shared__ float Bs[32 * 68];
    __shared__ float Ts[64 * 65];
    const int t = threadIdx.x;
    const int tx = t & 15, ty = t >> 4;
    const int row0 = blockIdx.y * 64;
    const int e0 = blockIdx.x * 64;
    unsigned long long acc[4][2] = {};
    for (int k0 = 0; k0 < D_; k0 += 32) {
#pragma unroll
        for (int p = 0; p < 2; p++) {
            int idx = p * 256 + t, r = idx >> 3, q = idx & 7;
            *(float4*)&As[r * 36 + q * 4] =
                *(const float4*)&val[(size_t)(row0 + r) * D_ + k0 + q * 4];
        }
#pragma unroll
        for (int p = 0; p < 2; p++) {
            int idx = p * 256 + t, kr = idx >> 4, ec = idx & 15;
            *(float4*)&Bs[kr * 68 + ec * 4] =
                *(const float4*)&Wv[(k0 + kr) * D_ + e0 + ec * 4];
        }
        __syncthreads();
#pragma unroll 16
        for (int kk = 0; kk < 32; kk++) {
            V4 bv; bv.f = *(float4*)&Bs[kk * 68 + tx * 4];
#pragma unroll
            for (int i = 0; i < 4; i++) {
                unsigned long long a2 = dup2(As[(ty * 4 + i) * 36 + kk]);
                acc[i][0] = ffma2(a2, bv.u[0], acc[i][0]);
                acc[i][1] = ffma2(a2, bv.u[1], acc[i][1]);
            }
        }
        __syncthreads();
    }
#pragma unroll
    for (int i = 0; i < 4; i++) {
        V4 o; o.u[0] = acc[i][0]; o.u[1] = acc[i][1];
        float v4[4] = {o.f.x, o.f.y, o.f.z, o.f.w};
#pragma unroll
        for (int q = 0; q < 4; q++)
            Ts[(tx * 4 + q) * 65 + ty * 4 + i] = v4[q];
    }
    __syncthreads();
    {
        const int b = row0 >> 12, m0l = row0 & (N_ - 1);
        const int e_l = t >> 2, ms = (t & 3) * 16;
        unsigned hw[8];
#pragma unroll
        for (int jj = 0; jj < 8; jj++)
            hw[jj] = pack_h2(Ts[e_l * 65 + ms + 2 * jj], Ts[e_l * 65 + ms + 2 * jj + 1]);
        size_t o = ((size_t)(b * D_ + e0 + e_l)) * N_ + m0l + ms;
        *(uint4*)(g_pthi + o)     = make_uint4(hw[0], hw[1], hw[2], hw[3]);
        *(uint4*)(g_pthi + o + 8) = make_uint4(hw[4], hw[5], hw[6], hw[7]);
    }
}

__global__ __launch_bounds__(256)
void split_val(const float* __restrict__ val) {
    size_t i = ((size_t)blockIdx.x * 256 + threadIdx.x) * 4;
    float4 v = *(const float4*)(val + i);
    float a[4] = {v.x, v.y, v.z, v.w};
#pragma unroll
    for (int k = 0; k < 4; k += 2) {
        __half h0 = __float2half_rn(a[k]);
        __half h1 = __float2half_rn(a[k + 1]);
        __half2 hp; hp.x = h0; hp.y = h1;
        __half2 lp;
        lp.x = __float2half_rn(a[k] - __half2float(h0));
        lp.y = __float2half_rn(a[k + 1] - __half2float(h1));
        *(__half2*)(g_vhi + i + k) = hp;
        *(__half2*)(g_vlo + i + k) = lp;
    }
}

// ================= kernel 1: scores -> E (upper triangle + mirror) =================
// grid (16 pairs, 2 j-halves, 4 batches) = 128 CTAs, 512 threads.
#define SE_VIH 0u          // Vi_hi 128 x 512B swizzled
#define SE_VIL 65536u      // Vi_lo
#define SE_VJ  131072u     // Vj_hi double buffer 2 x 32768 (64 rows x 512B)
#define SE_ES  196608u     // E staging 128 x 136B
#define SE_SZ  214016u

__global__ __launch_bounds__(512, 1)
void score_kernel() {
    extern __shared__ __align__(128) char sm[];
    const unsigned sb = smem_u32(sm);
    const int t = threadIdx.x, lane = t & 31, w = t >> 5;
    const int rg = w >> 1, ch = w & 1;       // 8 rg (m16) x 2 ch (n32)
    const int RG = rg * 16;
    const int p = blockIdx.x, hh = blockIdx.y, b = blockIdx.z;
    const __half* vh = g_vhi + (size_t)b * N_ * D_;
    const __half* vl = g_vlo + (size_t)b * N_ * D_;
    __half* gE = g_E + (size_t)b * N_ * N_;

    const unsigned aRow = RG + (lane & 15);
    const unsigned aK   = ((unsigned)lane >> 4) * 16;
    const unsigned aSw  = (aRow & 7) << 4;
    const unsigned aBase = aRow * 512;
    const unsigned bR0 = (unsigned)(ch * 32) + (((unsigned)lane >> 4) << 3) + (lane & 7);
    const unsigned bR1 = bR0 + 16;
    const unsigned bK  = (((unsigned)lane >> 3) & 1) * 16;
    const int r = lane >> 2, c2 = (lane & 3) * 2;

    for (int phase = 0; phase < 2; phase++) {
        const int bi = phase ? 31 - p : p;
        const int half_cnt = 32 - bi;
        const int cBeg = hh * half_cnt;
        const int cEnd = cBeg + half_cnt;
        const int base = 128 * bi;

        __syncthreads();
#pragma unroll
        for (int j = 0; j < 8; j++) {
            int idx = j * 512 + t, row = idx >> 5, kc = idx & 31;
            unsigned swz = (unsigned)(row * 512) + (((unsigned)kc * 16) ^ (((unsigned)row & 7) << 4));
            cpa16(sb + SE_VIH + swz, vh + (size_t)(base + row) * D_ + kc * 8);
            cpa16(sb + SE_VIL + swz, vl + (size_t)(base + row) * D_ + kc * 8);
        }
        {
            int c0 = base + cBeg * 64;
            unsigned vb = sb + SE_VJ + (unsigned)(cBeg & 1) * 32768u;
#pragma unroll
            for (int j = 0; j < 4; j++) {
                int idx = j * 512 + t, row = idx >> 5, kc = idx & 31;
                unsigned swz = (unsigned)(row * 512) + (((unsigned)kc * 16) ^ (((unsigned)row & 7) << 4));
                cpa16(vb + swz, vh + (size_t)(c0 + row) * D_ + kc * 8);
            }
        }
        CP_COMMIT();

        for (int cc = cBeg; cc < cEnd; cc++) {
            const int c0 = base + cc * 64;
            CP_WAIT0();
            __syncthreads();

            {
                int cnx = (cc + 1 < cEnd) ? cc + 1 : cc;
                int cn0 = base + cnx * 64;
                unsigned vb = sb + SE_VJ + (unsigned)((cc + 1) & 1) * 32768u;
#pragma unroll
                for (int j = 0; j < 4; j++) {
                    int idx = j * 512 + t, row = idx >> 5, kc = idx & 31;
                    unsigned swz = (unsigned)(row * 512) + (((unsigned)kc * 16) ^ (((unsigned)row & 7) << 4));
                    cpa16(vb + swz, vh + (size_t)(cn0 + row) * D_ + kc * 8);
                }
                CP_COMMIT();
            }

            const unsigned vjb = sb + SE_VJ + (unsigned)(cc & 1) * 32768u;
            float accS[16];
#pragma unroll
            for (int q = 0; q < 16; q++) accS[q] = 0.f;
#pragma unroll
            for (int ks = 0; ks < 16; ks++) {
                unsigned ah[4], al[4], b0[4], b1[4];
                unsigned ka = ((unsigned)(ks * 32) + aK) ^ aSw;
                ldm4(ah, sb + SE_VIH + aBase + ka);
                ldm4(al, sb + SE_VIL + aBase + ka);
                unsigned kb0 = ((unsigned)(ks * 32) + bK) ^ ((bR0 & 7) << 4);
                unsigned kb1 = ((unsigned)(ks * 32) + bK) ^ ((bR1 & 7) << 4);
                ldm4(b0, vjb + bR0 * 512 + kb0);
                ldm4(b1, vjb + bR1 * 512 + kb1);
                mmah(accS + 0,  ah, b0[0], b0[1]);
                mmah(accS + 8,  ah, b1[0], b1[1]);
                mmah(accS + 4,  ah, b0[2], b0[3]);
                mmah(accS + 12, ah, b1[2], b1[3]);
                mmah(accS + 0,  al, b0[0], b0[1]);
                mmah(accS + 8,  al, b1[0], b1[1]);
                mmah(accS + 4,  al, b0[2], b0[3]);
                mmah(accS + 12, al, b1[2], b1[3]);
            }

            const bool mirror = (c0 >= base + 128);
#pragma unroll
            for (int q = 0; q < 4; q++) {
                int colq = ch * 32 + (q >> 1) * 16 + (q & 1) * 8 + c2;
                float e0 = softsign(accS[q * 4 + 0]);
                float e1 = softsign(accS[q * 4 + 1]);
                float e2 = softsign(accS[q * 4 + 2]);
                float e3 = softsign(accS[q * 4 + 3]);
                unsigned h01 = pack_h2(e0, e1);
                unsigned h23 = pack_h2(e2, e3);
                *reinterpret_cast<unsigned*>(gE + (size_t)(base + RG + r) * N_ + c0 + colq)     = h01;
                *reinterpret_cast<unsigned*>(gE + (size_t)(base + RG + r + 8) * N_ + c0 + colq) = h23;
                if (mirror) {
                    sts32(sb + SE_ES + (unsigned)(RG + r) * 136 + colq * 2, h01);
                    sts32(sb + SE_ES + (unsigned)(RG + r + 8) * 136 + colq * 2, h23);
                }
            }
            if (mirror) {
                __syncthreads();
#pragma unroll
                for (int jp = 0; jp < 2; jp++) {
                    int cc2 = w * 4 + jp * 2;
#pragma unroll
                    for (int rg4 = 0; rg4 < 4; rg4++) {
                        int rr = rg4 * 32 + lane;
                        unsigned v = lds32(sb + SE_ES + (unsigned)rr * 136 + cc2 * 2);
                        __half2 hv = *(__half2*)&v;
                        gE[(size_t)(c0 + cc2) * N_ + base + rr]     = hv.x;
                        gE[(size_t)(c0 + cc2 + 1) * N_ + base + rr] = hv.y;
                    }
                }
            }
        }
    }
}

// ================= kernel 2: dval = E @ P, dstate = E @ state =================
// 256 threads / 8 warps, n-tile 64 rows, m-chunk 64, grid (64, 4) = 256 CTAs, 2 CTAs/SM.
// Row stride 144B (128B data + 16 pad). E db 2x9216, Pt db 2x36864.
#define K2_EB 0u
#define K2_PT 18432u
#define K2_SZ 92160u

__global__ __launch_bounds__(256, 2)
void dval_kernel(const float* __restrict__ state, float* __restrict__ out) {
    extern __shared__ __align__(128) char sm[];
    const unsigned sb = smem_u32(sm);
    const int t = threadIdx.x, lane = t & 31, w = t >> 5;
    const int rg2 = w >> 2, ch2 = w & 3;     // 2 rg2 (m32) x 4 ch2 (e64)
    const int RG2 = rg2 * 32;
    const int b = blockIdx.y;
    const int n0 = blockIdx.x * 64;

    const __half* pth = g_pthi + (size_t)b * D_ * N_;
    const __half* gEb = g_E + (size_t)b * N_ * N_;
    const float* stb = state + b * N_;

    // fragment addresses (144B row stride)
    const unsigned eB0 = (unsigned)(RG2 + (lane & 15)) * 144 + ((unsigned)lane >> 4) * 16;
    const unsigned eB1 = eB0 + 16 * 144;
    const unsigned pB  = ((unsigned)(ch2 * 64) + (((unsigned)lane >> 4) << 3) + (lane & 7)) * 144
                       + (((unsigned)lane >> 3) & 1) * 16;
    const int r = lane >> 2, c = (lane & 3) * 2;

    float accD[64];
#pragma unroll
    for (int q = 0; q < 64; q++) accD[q] = 0.f;
    float ds[4] = {0.f, 0.f, 0.f, 0.f};

    // prologue: E[0] (64x64), Pt[0] (256x64) into buf0
    {
#pragma unroll
        for (int j = 0; j < 2; j++) {
            int idx = j * 256 + t, row = idx >> 3, seg = idx & 7;
            cpa16(sb + K2_EB + (unsigned)(row * 144 + seg * 16),
                  gEb + (size_t)(n0 + row) * N_ + seg * 8);
        }
#pragma unroll
        for (int j = 0; j < 8; j++) {
            int idx = j * 256 + t, prow = idx >> 3, kc = idx & 7;
            cpa16(sb + K2_PT + (unsigned)(prow * 144 + kc * 16),
                  pth + (size_t)prow * N_ + kc * 8);
        }
    }
    CP_COMMIT();

#pragma unroll 1
    for (int i = 0; i < 64; i++) {
        const int m0 = i * 64;
        CP_WAIT0();
        __syncthreads();

        // prefetch m-chunk i+1 (clamped); one commit group
        const int m1 = (i < 63) ? m0 + 64 : 0;
        {
            unsigned enx = sb + K2_EB + (unsigned)((i + 1) & 1) * 9216u;
            unsigned pnx = sb + K2_PT + (unsigned)((i + 1) & 1) * 36864u;
#pragma unroll
            for (int j = 0; j < 2; j++) {
                int idx = j * 256 + t, row = idx >> 3, seg = idx & 7;
                cpa16(enx + (unsigned)(row * 144 + seg * 16),
                      gEb + (size_t)(n0 + row) * N_ + m1 + seg * 8);
            }
#pragma unroll
            for (int j = 0; j < 8; j++) {
                int idx = j * 256 + t, prow = idx >> 3, kc = idx & 7;
                cpa16(pnx + (unsigned)(prow * 144 + kc * 16),
                      pth + (size_t)prow * N_ + m1 + kc * 8);
            }
            CP_COMMIT();
        }

        const unsigned eb = sb + K2_EB + (unsigned)(i & 1) * 9216u;
        const unsigned pb = sb + K2_PT + (unsigned)(i & 1) * 36864u;
#pragma unroll
        for (int ks = 0; ks < 4; ks++) {
            unsigned eh0[4], eh1[4];
            ldm4(eh0, eb + eB0 + ks * 32);
            ldm4(eh1, eb + eB1 + ks * 32);
            // dstate accumulation (ch2==0 warps own rows exclusively)
            if (ch2 == 0) {
                const int mk = m0 + ks * 16;
                float2 fa = *(const float2*)(stb + mk + c);
                float2 fb = *(const float2*)(stb + mk + c + 8);
                float2 e;
                e = __half22float2(*(__half2*)&eh0[0]); ds[0] += e.x * fa.x + e.y * fa.y;
                e = __half22float2(*(__half2*)&eh0[1]); ds[1] += e.x * fa.x + e.y * fa.y;
                e = __half22float2(*(__half2*)&eh0[2]); ds[0] += e.x * fb.x + e.y * fb.y;
                e = __half22float2(*(__half2*)&eh0[3]); ds[1] += e.x * fb.x + e.y * fb.y;
                e = __half22float2(*(__half2*)&eh1[0]); ds[2] += e.x * fa.x + e.y * fa.y;
                e = __half22float2(*(__half2*)&eh1[1]); ds[3] += e.x * fa.x + e.y * fa.y;
                e = __half22float2(*(__half2*)&eh1[2]); ds[2] += e.x * fb.x + e.y * fb.y;
                e = __half22float2(*(__half2*)&eh1[3]); ds[3] += e.x * fb.x + e.y * fb.y;
            }
#pragma unroll
            for (int g = 0; g < 4; g++) {
                unsigned ph[4];
                unsigned po = pB + (unsigned)(g * 16 * 144 + ks * 32);
                ldm4(ph, pb + po);
                float* d00 = accD + ((0 * 4 + g) * 2 + 0) * 4;
                float* d01 = accD + ((0 * 4 + g) * 2 + 1) * 4;
                float* d10 = accD + ((1 * 4 + g) * 2 + 0) * 4;
                float* d11 = accD + ((1 * 4 + g) * 2 + 1) * 4;
                mmah(d00, eh0, ph[0], ph[1]);
                mmah(d10, eh1, ph[0], ph[1]);
                mmah(d01, eh0, ph[2], ph[3]);
                mmah(d11, eh1, ph[2], ph[3]);
            }
        }
    }

    // -------- write delta_val --------
    float* dvb = out + B_ * N_ + ((size_t)(b * N_ + n0)) * D_;
#pragma unroll
    for (int s = 0; s < 2; s++) {
#pragma unroll
        for (int g = 0; g < 4; g++) {
#pragma unroll
            for (int h2 = 0; h2 < 2; h2++) {
                int row = RG2 + s * 16 + r;
                int col = ch2 * 64 + g * 16 + h2 * 8 + c;
                const float* d = accD + ((s * 4 + g) * 2 + h2) * 4;
                float2 lo; lo.x = d[0]; lo.y = d[1];
                float2 hi; hi.x = d[2]; hi.y = d[3];
                *(float2*)(dvb + (size_t)row * D_ + col) = lo;
                *(float2*)(dvb + (size_t)(row + 8) * D_ + col) = hi;
            }
        }
    }

    // -------- reduce & write delta_state (no atomics; ch2==0 warps own 32 rows each) --------
    if (ch2 == 0) {
#pragma unroll
        for (int j = 0; j < 4; j++) {
            ds[j] += __shfl_xor_sync(0xffffffffu, ds[j], 1);
            ds[j] += __shfl_xor_sync(0xffffffffu, ds[j], 2);
        }
        if ((lane & 3) == 0) {
#pragma unroll
            for (int j = 0; j < 4; j++)
                out[b * N_ + n0 + RG2 + j * 8 + r] = ds[j];
        }
    }
}

extern "C" void kernel_launch(void* const* d_in, const int* in_sizes, int n_in,
                              void* d_out, int out_size) {
    const float* val   = (const float*)d_in[0];  // [B, N, D]
    const float* state = (const float*)d_in[1];  // [B, N]
    const float* Wv    = (const float*)d_in[2];  // [D, D]
    float* out = (float*)d_out;                  // [B*N] delta_state, [B*N*D] delta_val
    (void)in_sizes; (void)n_in; (void)out_size;

    cudaFuncSetAttribute(score_kernel, cudaFuncAttributeMaxDynamicSharedMemorySize, SE_SZ);
    cudaFuncSetAttribute(dval_kernel,  cudaFuncAttributeMaxDynamicSharedMemorySize, K2_SZ);

    split_val<<<(B_ * N_ * D_) / 1024, 256>>>(val);
    proj_kernel<<<dim3(D_ / 64, (B_ * N_) / 64), 256>>>(val, Wv);
    score_kernel<<<dim3(16, 2, 4), 512, SE_SZ>>>();
    dval_kernel<<<dim3(N_ / 64, B_), 256, K2_SZ>>>(state, out);
}